// round 6
// baseline (speedup 1.0000x reference)
#include <cuda_runtime.h>
#include <cuda_fp16.h>

namespace {

constexpr int Hh = 8, Ll = 2048, Dd = 512;
constexpr float PIf = 3.14159265358979323846f;
using u64 = unsigned long long;

// ---- packed f32x2 complex ops (re in lane0, im in lane1) -------------------
__device__ __forceinline__ u64 pk2(float x, float y) {
  u64 r; asm("mov.b64 %0, {%1, %2};" : "=l"(r) : "f"(x), "f"(y)); return r;
}
__device__ __forceinline__ void unpk(u64 v, float& x, float& y) {
  asm("mov.b64 {%0, %1}, %2;" : "=f"(x), "=f"(y) : "l"(v));
}
__device__ __forceinline__ u64 padd(u64 a, u64 b) {
  u64 r; asm("add.rn.f32x2 %0, %1, %2;" : "=l"(r) : "l"(a), "l"(b)); return r;
}
__device__ __forceinline__ u64 pmul(u64 a, u64 b) {
  u64 r; asm("mul.rn.f32x2 %0, %1, %2;" : "=l"(r) : "l"(a), "l"(b)); return r;
}
__device__ __forceinline__ u64 pfma(u64 a, u64 b, u64 c) {
  u64 r; asm("fma.rn.f32x2 %0, %1, %2, %3;" : "=l"(r) : "l"(a), "l"(b), "l"(c)); return r;
}
__device__ __forceinline__ u64 pswap(u64 v) { float x, y; unpk(v, x, y); return pk2(y, x); }
template<int S>
__device__ __forceinline__ u64 prot(u64 v) {   // * -i (S<0) or * +i (S>0)
  float x, y; unpk(v, x, y);
  return (S < 0) ? pk2(y, -x) : pk2(-y, x);
}
// scalar-twiddle complex multiply on a packed value
__device__ __forceinline__ u64 cmulsc(u64 v, float c, float s) {
  float x, y; unpk(v, x, y);
  return pk2(x * c - y * s, x * s + y * c);
}

// fp16 exchange pack/unpack: one complex = one half2 = 4 bytes
__device__ __forceinline__ unsigned pkh(u64 v) {
  float x, y; unpk(v, x, y);
  __half2 h = __floats2half2_rn(x, y);
  return *reinterpret_cast<unsigned*>(&h);
}
__device__ __forceinline__ u64 uph(unsigned u) {
  __half2 h = *reinterpret_cast<__half2*>(&u);
  float2 f = __half22float2(h);
  return pk2(f.x, f.y);
}

// 8-point DFT on packed values, natural order. S=-1 forward, +1 inverse.
template<int S>
__device__ __forceinline__ void dft8p(u64 v[8]) {
  const float r = 0.70710678118654752440f;
  const u64 NEG1 = pk2(-1.f, -1.f);
  const u64 PM   = pk2( 1.f, -1.f);
  const u64 MP   = pk2(-1.f,  1.f);
  const u64 RR   = pk2(  r,    r);
  const u64 NR   = pk2( -r,   -r);
  auto psub = [&](u64 a, u64 b) { return pfma(b, NEG1, a); };

  u64 a0 = padd(v[0], v[4]), a1 = padd(v[1], v[5]);
  u64 a2 = padd(v[2], v[6]), a3 = padd(v[3], v[7]);
  u64 b0 = psub(v[0], v[4]), b1 = psub(v[1], v[5]);
  u64 b2 = psub(v[2], v[6]), b3 = psub(v[3], v[7]);

  b1 = pmul(pfma(pswap(b1), (S < 0) ? PM : MP, b1), RR);   // *W8^S
  b3 = pmul(pfma(pswap(b3), (S < 0) ? MP : PM, b3), NR);   // *W8^{3S}
  b2 = prot<S>(b2);

  {
    u64 e0 = padd(a0, a2), e1 = padd(a1, a3);
    u64 o0 = psub(a0, a2), t1 = psub(a1, a3);
    u64 o1 = prot<S>(t1);
    v[0] = padd(e0, e1); v[4] = psub(e0, e1);
    v[2] = padd(o0, o1); v[6] = psub(o0, o1);
  }
  {
    u64 e0 = padd(b0, b2), e1 = padd(b1, b3);
    u64 o0 = psub(b0, b2), t1 = psub(b1, b3);
    u64 o1 = prot<S>(t1);
    v[1] = padd(e0, e1); v[5] = psub(e0, e1);
    v[3] = padd(o0, o1); v[7] = psub(o0, o1);
  }
}

// Geometric twiddle stage: v[k] *= e^{i k th}, k=1..7.
// Odd harmonics from MUFU, evens by double-angle squaring.
__device__ __forceinline__ void twiddle8(u64 v[8], float th) {
  float c1, s1; __sincosf(th, &s1, &c1);
  v[1] = cmulsc(v[1], c1, s1);
  float c2 = c1 * c1 - s1 * s1, s2 = 2.f * c1 * s1;
  v[2] = cmulsc(v[2], c2, s2);
  float c3, s3; __sincosf(3.f * th, &s3, &c3);
  v[3] = cmulsc(v[3], c3, s3);
  float c4 = c2 * c2 - s2 * s2, s4 = 2.f * c2 * s2;
  v[4] = cmulsc(v[4], c4, s4);
  float c5, s5; __sincosf(5.f * th, &s5, &c5);
  v[5] = cmulsc(v[5], c5, s5);
  float c6 = c3 * c3 - s3 * s3, s6 = 2.f * c3 * s3;
  v[6] = cmulsc(v[6], c6, s6);
  float c7, s7; __sincosf(7.f * th, &s7, &c7);
  v[7] = cmulsc(v[7], c7, s7);
}

// Full-warp conflict-free swizzle for 4B exchange values, logical index
// 64a + 8b + c (a,b,c in 0..7).
// phys = (a2 | b2 b1 b0 | a1^b1 | a0^b0 | (b^c)[2:0]); bank bits = low 5.
// Restricted to each exchange pattern's 5 free lane bits within a warp
// (S1 {b1,b0,c}, S2 {a1,a0,c}, S3 {a1,a0,b}) the low-5 map is invertible =>
// 32 lanes hit 32 distinct banks => 1 wavefront per 4B instruction.
__device__ __forceinline__ int swz16(int a, int b, int c) {
  return ((a >> 2) << 8) | (b << 5)
       | ((((a >> 1) ^ (b >> 1)) & 1) << 4)
       | (((a ^ b) & 1) << 3) | ((b ^ c) & 7);
}

// 8B swizzle for the fp32 gate array (half-warp conflict-free, as before).
__device__ __forceinline__ int swz(int a, int b, int c) {
  return ((a >> 1) << 7) | ((b >> 1) << 5) | ((b & 1) << 4)
       | (((a ^ b) & 1) << 3) | ((b ^ c) & 7);
}

// One block = one (h,l): 4 pair-rows (s pairs batches s and s+4),
// 64 threads per pair-row. Radix-8 FFT512 (DIF fwd, digit-rev spectrum,
// DIT inv). Exchanges via fp16 half2 smem; gate staged in fp32 smem.
__global__ void __launch_bounds__(256, 6)
sgn_fft_kernel(const float* __restrict__ x, const float* __restrict__ wgt,
               float* __restrict__ out)
{
  __shared__ unsigned smh[4][512];   // half2 exchange buffers (8 KB)
  __shared__ float2 Vsm[512];        // fp32 gate (4 KB)

  const int tid = threadIdx.x;
  const int s   = tid >> 6;
  const int t   = tid & 63;
  const int hl  = blockIdx.x;          // hl = h*2048 + l

  const float2* __restrict__ wrow =
      reinterpret_cast<const float2*>(wgt) + (size_t)hl * Dd;

  // V_k = (W_k + conj(W_{-k})) / 1024, stored at phys(a=k2,b=k1,c=k0).
#pragma unroll
  for (int i = tid; i < 512; i += 256) {
    float2 wk = __ldg(&wrow[i]);
    float2 wm = __ldg(&wrow[(512 - i) & 511]);
    Vsm[swz(i >> 6, (i >> 3) & 7, i & 7)] =
        make_float2((wk.x + wm.x) * (1.f / 1024.f),
                    (wk.y - wm.y) * (1.f / 1024.f));
  }

  // 32-bit element offsets (B*H*L*D = 2^26 < 2^31)
  const unsigned rowStride = (unsigned)(Hh * Ll) * (unsigned)Dd; // per-batch
  const unsigned base = (unsigned)hl * (unsigned)Dd;
  const unsigned off1 = (unsigned)s * rowStride + base;
  const unsigned off2 = off1 + 4u * rowStride;
  const float* __restrict__ x1 = x + off1;
  const float* __restrict__ x2 = x + off2;

  u64 v[8];
  // z = x1 + i*x2, n = 64*n2 + t
#pragma unroll
  for (int n2 = 0; n2 < 8; ++n2)
    v[n2] = pk2(__ldg(&x1[(n2 << 6) + t]), __ldg(&x2[(n2 << 6) + t]));

  // ---- forward stage 1: DFT over n2 -> k0, twiddle e^{-2pi i t k0/512}
  dft8p<-1>(v);
  twiddle8(v, -2.f * PIf * (float)t * (1.f / 512.f));
  {
    const int n1 = t >> 3, n0 = t & 7;
#pragma unroll
    for (int k = 0; k < 8; ++k) smh[s][swz16(k, n1, n0)] = pkh(v[k]);
  }
  __syncthreads();

  // ---- forward stage 2: thread (k0, n0), DFT over n1 -> k1, tw e^{-2pi i n0 k1/64}
  const int k0 = t >> 3;
  const int n0 = t & 7;
#pragma unroll
  for (int j = 0; j < 8; ++j) v[j] = uph(smh[s][swz16(k0, j, n0)]);
  dft8p<-1>(v);
  twiddle8(v, -2.f * PIf * (float)n0 * (1.f / 64.f));
#pragma unroll
  for (int k = 0; k < 8; ++k) smh[s][swz16(k0, k, n0)] = pkh(v[k]);
  __syncthreads();

  // ---- forward stage 3 (registers): thread (k0, k1), DFT over n0 -> k2
  const int k1 = t & 7;
#pragma unroll
  for (int c = 0; c < 8; ++c) v[c] = uph(smh[s][swz16(k0, k1, c)]);
  dft8p<-1>(v);
  // v[k2] = Z[k] at k = k0 + 8*k1 + 64*k2

  // ---- spectral gate (conflict-free fp32 smem)
#pragma unroll
  for (int k2 = 0; k2 < 8; ++k2) {
    float2 Vv = Vsm[swz(k2, k1, k0)];
    v[k2] = cmulsc(v[k2], Vv.x, Vv.y);
  }

  // ---- inverse stage 3': IDFT over k2 -> n0', twiddle e^{+2pi i n0' k1/64}
  dft8p<1>(v);
  twiddle8(v, 2.f * PIf * (float)k1 * (1.f / 64.f));
#pragma unroll
  for (int c = 0; c < 8; ++c) smh[s][swz16(k0, k1, c)] = pkh(v[c]);
  __syncthreads();

  // ---- inverse stage 2': thread (k0, n0), IDFT over k1 -> n1,
  //      twiddle e^{+2pi i (8*n1+n0)*k0/512}
#pragma unroll
  for (int j = 0; j < 8; ++j) v[j] = uph(smh[s][swz16(k0, j, n0)]);
  dft8p<1>(v);
  {
    float s0, c0; __sincosf(2.f * PIf * (float)(k0 * n0) * (1.f / 512.f), &s0, &c0);
    float s1, c1; __sincosf(2.f * PIf * (float)k0 * (1.f / 64.f), &s1, &c1);
    float cc = c0, ss = s0;
#pragma unroll
    for (int n1 = 0; n1 < 8; ++n1) {
      v[n1] = cmulsc(v[n1], cc, ss);
      if (n1 < 7) { float nc = cc * c1 - ss * s1; ss = cc * s1 + ss * c1; cc = nc; }
    }
  }
#pragma unroll
  for (int n1 = 0; n1 < 8; ++n1) smh[s][swz16(k0, n1, n0)] = pkh(v[n1]);
  __syncthreads();

  // ---- inverse stage 1': thread t=(n1,n0), IDFT over k0 -> n2, store
#pragma unroll
  for (int a = 0; a < 8; ++a) v[a] = uph(smh[s][swz16(a, t >> 3, t & 7)]);
  dft8p<1>(v);

  float* __restrict__ o1 = out + off1;
  float* __restrict__ o2 = out + off2;
#pragma unroll
  for (int n2 = 0; n2 < 8; ++n2) {
    float re, im; unpk(v[n2], re, im);
    o1[(n2 << 6) + t] = re;   // Re -> batch s
    o2[(n2 << 6) + t] = im;   // Im -> batch s+4
  }
}

} // namespace

extern "C" void kernel_launch(void* const* d_in, const int* in_sizes, int n_in,
                              void* d_out, int out_size) {
  const float* x   = (const float*)d_in[0];
  // d_in[1] is the (unused) mask
  const float* wgt = (const float*)d_in[2];
  float* out       = (float*)d_out;
  sgn_fft_kernel<<<Hh * Ll, 256>>>(x, wgt, out);
}

// round 7
// speedup vs baseline: 1.0624x; 1.0624x over previous
#include <cuda_runtime.h>

namespace {

constexpr int Hh = 8, Ll = 2048, Dd = 512;
constexpr float PIf = 3.14159265358979323846f;
using u64 = unsigned long long;

// ---- packed f32x2 complex ops (re in lane0, im in lane1) -------------------
__device__ __forceinline__ u64 pk2(float x, float y) {
  u64 r; asm("mov.b64 %0, {%1, %2};" : "=l"(r) : "f"(x), "f"(y)); return r;
}
__device__ __forceinline__ void unpk(u64 v, float& x, float& y) {
  asm("mov.b64 {%0, %1}, %2;" : "=f"(x), "=f"(y) : "l"(v));
}
__device__ __forceinline__ u64 padd(u64 a, u64 b) {
  u64 r; asm("add.rn.f32x2 %0, %1, %2;" : "=l"(r) : "l"(a), "l"(b)); return r;
}
__device__ __forceinline__ u64 pmul(u64 a, u64 b) {
  u64 r; asm("mul.rn.f32x2 %0, %1, %2;" : "=l"(r) : "l"(a), "l"(b)); return r;
}
__device__ __forceinline__ u64 pfma(u64 a, u64 b, u64 c) {
  u64 r; asm("fma.rn.f32x2 %0, %1, %2, %3;" : "=l"(r) : "l"(a), "l"(b), "l"(c)); return r;
}
__device__ __forceinline__ u64 pswap(u64 v) { float x, y; unpk(v, x, y); return pk2(y, x); }
template<int S>
__device__ __forceinline__ u64 prot(u64 v) {   // * -i (S<0) or * +i (S>0)
  float x, y; unpk(v, x, y);
  return (S < 0) ? pk2(y, -x) : pk2(-y, x);
}
// scalar-twiddle complex multiply on a packed value
__device__ __forceinline__ u64 cmulsc(u64 v, float c, float s) {
  float x, y; unpk(v, x, y);
  return pk2(x * c - y * s, x * s + y * c);
}

// 8-point DFT on packed values, natural order. S=-1 forward, +1 inverse.
template<int S>
__device__ __forceinline__ void dft8p(u64 v[8]) {
  const float r = 0.70710678118654752440f;
  const u64 NEG1 = pk2(-1.f, -1.f);
  const u64 PM   = pk2( 1.f, -1.f);
  const u64 MP   = pk2(-1.f,  1.f);
  const u64 RR   = pk2(  r,    r);
  const u64 NR   = pk2( -r,   -r);
  auto psub = [&](u64 a, u64 b) { return pfma(b, NEG1, a); };

  u64 a0 = padd(v[0], v[4]), a1 = padd(v[1], v[5]);
  u64 a2 = padd(v[2], v[6]), a3 = padd(v[3], v[7]);
  u64 b0 = psub(v[0], v[4]), b1 = psub(v[1], v[5]);
  u64 b2 = psub(v[2], v[6]), b3 = psub(v[3], v[7]);

  b1 = pmul(pfma(pswap(b1), (S < 0) ? PM : MP, b1), RR);   // *W8^S
  b3 = pmul(pfma(pswap(b3), (S < 0) ? MP : PM, b3), NR);   // *W8^{3S}
  b2 = prot<S>(b2);

  {
    u64 e0 = padd(a0, a2), e1 = padd(a1, a3);
    u64 o0 = psub(a0, a2), t1 = psub(a1, a3);
    u64 o1 = prot<S>(t1);
    v[0] = padd(e0, e1); v[4] = psub(e0, e1);
    v[2] = padd(o0, o1); v[6] = psub(o0, o1);
  }
  {
    u64 e0 = padd(b0, b2), e1 = padd(b1, b3);
    u64 o0 = psub(b0, b2), t1 = psub(b1, b3);
    u64 o1 = prot<S>(t1);
    v[1] = padd(e0, e1); v[5] = psub(e0, e1);
    v[3] = padd(o0, o1); v[7] = psub(o0, o1);
  }
}

// Geometric twiddle stage: v[k] *= e^{i k th}, k=1..7.
// Odd harmonics from MUFU (__sincosf), evens by double-angle squaring.
__device__ __forceinline__ void twiddle8(u64 v[8], float th) {
  float c1, s1; __sincosf(th, &s1, &c1);
  v[1] = cmulsc(v[1], c1, s1);
  float c2 = c1 * c1 - s1 * s1, s2 = 2.f * c1 * s1;
  v[2] = cmulsc(v[2], c2, s2);
  float c3, s3; __sincosf(3.f * th, &s3, &c3);
  v[3] = cmulsc(v[3], c3, s3);
  float c4 = c2 * c2 - s2 * s2, s4 = 2.f * c2 * s2;
  v[4] = cmulsc(v[4], c4, s4);
  float c5, s5; __sincosf(5.f * th, &s5, &c5);
  v[5] = cmulsc(v[5], c5, s5);
  float c6 = c3 * c3 - s3 * s3, s6 = 2.f * c3 * s3;
  v[6] = cmulsc(v[6], c6, s6);
  float c7, s7; __sincosf(7.f * th, &s7, &c7);
  v[7] = cmulsc(v[7], c7, s7);
}

// Half-warp phase-conflict-free swizzle for 8B values, logical 64a + 8b + c.
// phys [8:4] = (a2,a1,b2,b1,b0); [3:0] = (a0^b0, c2^b2, c1^b1, c0^b0).
// Invertible on each access pattern's half-warp free-bit subspace =>
// 2 wavefronts per 8B instruction (the floor) on every exchange and the gate.
__device__ __forceinline__ int swz(int a, int b, int c) {
  return ((a >> 1) << 7) | ((b >> 1) << 5) | ((b & 1) << 4)
       | (((a ^ b) & 1) << 3) | ((b ^ c) & 7);
}

// One block = one (h,l): 4 pair-rows (s pairs batches s and s+4),
// 64 threads per pair-row. Radix-8 FFT512 (DIF fwd, digit-rev spectrum,
// DIT inv). Gate staged in smem (swizzled digit-reversed layout).
__global__ void __launch_bounds__(256, 5)
sgn_fft_kernel(const float* __restrict__ x, const float* __restrict__ wgt,
               float* __restrict__ out)
{
  __shared__ u64 sm[4][512];
  __shared__ float2 Vsm[512];

  const int tid = threadIdx.x;
  const int s   = tid >> 6;
  const int t   = tid & 63;
  const int hl  = blockIdx.x;          // hl = h*2048 + l

  const float2* __restrict__ wrow =
      reinterpret_cast<const float2*>(wgt) + (size_t)hl * Dd;

  // V_k = (W_k + conj(W_{-k})) / 1024, stored at phys(a=k2,b=k1,c=k0).
#pragma unroll
  for (int i = tid; i < 512; i += 256) {
    float2 wk = __ldg(&wrow[i]);
    float2 wm = __ldg(&wrow[(512 - i) & 511]);
    Vsm[swz(i >> 6, (i >> 3) & 7, i & 7)] =
        make_float2((wk.x + wm.x) * (1.f / 1024.f),
                    (wk.y - wm.y) * (1.f / 1024.f));
  }

  // 32-bit element offsets (B*H*L*D = 2^26 < 2^31)
  const unsigned rowStride = (unsigned)(Hh * Ll) * (unsigned)Dd; // per-batch
  const unsigned base = (unsigned)hl * (unsigned)Dd;
  const unsigned off1 = (unsigned)s * rowStride + base;
  const unsigned off2 = off1 + 4u * rowStride;
  const float* __restrict__ x1 = x + off1;
  const float* __restrict__ x2 = x + off2;

  u64 v[8];
  // z = x1 + i*x2, n = 64*n2 + t
#pragma unroll
  for (int n2 = 0; n2 < 8; ++n2)
    v[n2] = pk2(__ldg(&x1[(n2 << 6) + t]), __ldg(&x2[(n2 << 6) + t]));

  // ---- forward stage 1: DFT over n2 -> k0, twiddle e^{-2pi i t k0/512}
  dft8p<-1>(v);
  twiddle8(v, -2.f * PIf * (float)t * (1.f / 512.f));
  {
    const int n1 = t >> 3, n0 = t & 7;
#pragma unroll
    for (int k = 0; k < 8; ++k) sm[s][swz(k, n1, n0)] = v[k];
  }
  __syncthreads();

  // ---- forward stage 2: thread (k0, n0), DFT over n1 -> k1, tw e^{-2pi i n0 k1/64}
  const int k0 = t >> 3;
  const int n0 = t & 7;
#pragma unroll
  for (int j = 0; j < 8; ++j) v[j] = sm[s][swz(k0, j, n0)];
  dft8p<-1>(v);
  twiddle8(v, -2.f * PIf * (float)n0 * (1.f / 64.f));
#pragma unroll
  for (int k = 0; k < 8; ++k) sm[s][swz(k0, k, n0)] = v[k];
  __syncthreads();

  // ---- forward stage 3 (registers): thread (k0, k1), DFT over n0 -> k2
  const int k1 = t & 7;
#pragma unroll
  for (int c = 0; c < 8; ++c) v[c] = sm[s][swz(k0, k1, c)];
  dft8p<-1>(v);
  // v[k2] = Z[k] at k = k0 + 8*k1 + 64*k2

  // ---- spectral gate (conflict-free smem)
#pragma unroll
  for (int k2 = 0; k2 < 8; ++k2) {
    float2 Vv = Vsm[swz(k2, k1, k0)];
    v[k2] = cmulsc(v[k2], Vv.x, Vv.y);
  }

  // ---- inverse stage 3': IDFT over k2 -> n0', twiddle e^{+2pi i n0' k1/64}
  dft8p<1>(v);
  twiddle8(v, 2.f * PIf * (float)k1 * (1.f / 64.f));
#pragma unroll
  for (int c = 0; c < 8; ++c) sm[s][swz(k0, k1, c)] = v[c];
  __syncthreads();

  // ---- inverse stage 2': thread (k0, n0), IDFT over k1 -> n1,
  //      twiddle e^{+2pi i (8*n1+n0)*k0/512} via direct MUFU sincos
  //      (angle <= 2pi*7*63/512 ~ 5.4 rad, safe for fast sincos)
#pragma unroll
  for (int j = 0; j < 8; ++j) v[j] = sm[s][swz(k0, j, n0)];
  dft8p<1>(v);
  {
    const float thb = 2.f * PIf * (1.f / 512.f) * (float)k0;
#pragma unroll
    for (int n1 = 0; n1 < 8; ++n1) {
      float sn, cs; __sincosf(thb * (float)((n1 << 3) + n0), &sn, &cs);
      v[n1] = cmulsc(v[n1], cs, sn);
    }
  }
#pragma unroll
  for (int n1 = 0; n1 < 8; ++n1) sm[s][swz(k0, n1, n0)] = v[n1];
  __syncthreads();

  // ---- inverse stage 1': thread t=(n1,n0), IDFT over k0 -> n2, store
#pragma unroll
  for (int a = 0; a < 8; ++a) v[a] = sm[s][swz(a, t >> 3, t & 7)];
  dft8p<1>(v);

  float* __restrict__ o1 = out + off1;
  float* __restrict__ o2 = out + off2;
#pragma unroll
  for (int n2 = 0; n2 < 8; ++n2) {
    float re, im; unpk(v[n2], re, im);
    o1[(n2 << 6) + t] = re;   // Re -> batch s
    o2[(n2 << 6) + t] = im;   // Im -> batch s+4
  }
}

} // namespace

extern "C" void kernel_launch(void* const* d_in, const int* in_sizes, int n_in,
                              void* d_out, int out_size) {
  const float* x   = (const float*)d_in[0];
  // d_in[1] is the (unused) mask
  const float* wgt = (const float*)d_in[2];
  float* out       = (float*)d_out;
  sgn_fft_kernel<<<Hh * Ll, 256>>>(x, wgt, out);
}